// round 11
// baseline (speedup 1.0000x reference)
#include <cuda_runtime.h>
#include <math.h>

#define BB  8
#define LL  512
#define KK  16
#define EE  32
#define NHH 64
#define GG  192
#define CH      16           // GRU: steps per GI prefetch chunk
#define NCHUNK  (LL/CH)      // 32
#define NBLK    136

// -------- scratch (static device globals; no runtime allocation) --------
__device__ float g_q[BB*LL*EE];
__device__ float g_k[BB*LL*EE];
__device__ int   g_bcnt[BB*KK];
__device__ int   g_boff[BB*KK];
__device__ int   g_bidxC[BB*LL];     // compacted buckets, per-b 512 entries
__device__ float g_M2[GG*KK];        // W_ih @ Wo   (192 x 16)
__device__ float g_cc[GG];           // W_ih @ bo + b_ih + b_hh
__device__ float g_GI[BB*LL*GG];     // precomputed input gates (biases folded)

// -------- monotone dataflow flags (never reset; run-scoped via ticket) ----
__device__ int g_ticket;
__device__ int g_proj_done[BB];      // +1 per finished proj slice (8 per run)
__device__ int g_bkt_done[BB];       // +1 per run
__device__ int g_fold_done;          // +1 per run
__device__ int g_attq[BB*16];        // +1 per (b, qtile) per run

__device__ __forceinline__ float tanh_fast(float x) {
    float y;
    asm("tanh.approx.f32 %0, %1;" : "=f"(y) : "f"(x));
    return y;
}
#define FMA2(acc, x, y) \
    asm("fma.rn.f32x2 %0, %1, %2, %0;" : "+l"(acc) : "l"(x), "l"(y))
__device__ __forceinline__ float f2lo(unsigned long long v) {
    return __uint_as_float((unsigned)v);
}
__device__ __forceinline__ float f2hi(unsigned long long v) {
    return __uint_as_float((unsigned)(v >> 32));
}

// acquire-spin on a monotone counter
__device__ __forceinline__ void waitcnt(const int* p, int target) {
    int v;
    for (;;) {
        asm volatile("ld.global.cg.b32 %0, [%1];" : "=r"(v) : "l"(p));
        if (v - target >= 0) break;
        __nanosleep(64);
    }
    __threadfence();
}

// smem layout for att path (floats):
#define SOFF_S    0                       // 32*512 score tile (also proj scratch)
#define SOFF_KB   16384                   // 64*36  k staging (stride 36)
#define SOFF_VAL  (SOFF_KB+2304)          // 512
#define SOFF_X    (SOFF_VAL+512)          // 512
#define SOFF_M2   (SOFF_X+512)            // 192*17
#define SOFF_CC   (SOFF_M2+3264)          // 192
#define SOFF_INT  (SOFF_CC+192)           // ints: cnt 16, off 16, bidx 512
#define SMEM_BYTES ((SOFF_INT + 544) * 4)

__global__ void __launch_bounds__(256) k_all(
        const float* __restrict__ ts,   const float* __restrict__ val,
        const int*   __restrict__ mark, const float* __restrict__ npm,
        const float* __restrict__ Wl, const float* __restrict__ bl,
        const float* __restrict__ Wp, const float* __restrict__ bp,
        const float* __restrict__ Wq, const float* __restrict__ bq,
        const float* __restrict__ Wk, const float* __restrict__ bk,
        const float* __restrict__ Wo, const float* __restrict__ bo,
        const float* __restrict__ W_ih, const float* __restrict__ W_hh,
        const float* __restrict__ b_ih, const float* __restrict__ b_hh,
        float* __restrict__ out) {
    extern __shared__ float sm[];
    __shared__ int run_s;
    int blk = blockIdx.x, tid = threadIdx.x;
    if (tid == 0) run_s = atomicAdd(&g_ticket, 1) / NBLK;
    __syncthreads();
    int run = run_s;

    if (blk < 128) {
        // ================= att block (qt, b) with embedded setup ============
        int qt = blk >> 3, b = blk & 7;
        int wid = tid >> 5, lane = tid & 31;

        // ---- stage 1: setup subtask ----
        if (qt < 8) {
            // proj slice: rows [qt*64, qt*64+64) of batch b
            float* ke_s = sm + SOFF_S;            // 64*33
            float* wq_s = ke_s + 64*33;           // 32*33
            float* wk_s = wq_s + EE*33;           // 32*33
            float* sWp  = wk_s + EE*33;           // 32
            float* sbp  = sWp + EE;               // 32
            float* sWls = sbp + EE;               // 2
            int rbase = qt * 64;

            for (int i = tid; i < EE*EE; i += 256) {
                int e = i >> 5, j = i & 31;
                wq_s[e*33+j] = Wq[i];
                wk_s[e*33+j] = Wk[i];
            }
            if (tid < EE-1) { sWp[tid] = Wp[tid]; sbp[tid] = bp[tid]; }
            if (tid == 0)   { sWls[0] = Wl[0]; sWls[1] = bl[0]; }
            __syncthreads();

            for (int idx = tid; idx < 64*EE; idx += 256) {
                int r = idx >> 5, i = idx & 31;
                float t = ts[b*LL + rbase + r];
                float v = (i == 0) ? fmaf(t, sWls[0], sWls[1])
                                   : __sinf(fmaf(t, sWp[i-1], sbp[i-1]));
                ke_s[r*33 + i] = v;
            }
            __syncthreads();

            int e = lane;                       // 8 warps x 8 rows
            float wq[EE], wk[EE];
            #pragma unroll
            for (int j = 0; j < EE; j++) { wq[j] = wq_s[e*33+j]; wk[j] = wk_s[e*33+j]; }
            float bqv = __ldg(&bq[e]), bkv = __ldg(&bk[e]);
            #pragma unroll
            for (int p = 0; p < 8; p++) {
                int r = wid*8 + p;
                float aq = bqv, ak = bkv;
                #pragma unroll
                for (int j = 0; j < EE; j++) {
                    float kv = ke_s[r*33+j];
                    aq = fmaf(wq[j], kv, aq);
                    ak = fmaf(wk[j], kv, ak);
                }
                int row = b*LL + rbase + r;
                g_q[row*EE + e] = aq;
                g_k[row*EE + e] = ak;
            }
            __threadfence();
            __syncthreads();
            if (tid == 0) atomicAdd(&g_proj_done[b], 1);
        } else if (qt == 8) {
            // compacted bucket build for batch b (8 warps, 2 categories each)
            __shared__ int cnt_sh[KK], off_sh[KK];
            unsigned mrec[2][LL/32];
            #pragma unroll
            for (int pass = 0; pass < 2; pass++) {
                int c = wid + pass*8;
                int cnt = 0;
                #pragma unroll
                for (int ch = 0; ch < LL/32; ch++) {
                    int k = ch*32 + lane;
                    int   mk = mark[b*LL+k];
                    float np = npm[b*LL+k];
                    bool hit = (mk == c+1) && (np > 0.f);
                    unsigned m = __ballot_sync(0xffffffffu, hit);
                    mrec[pass][ch] = m;
                    cnt += __popc(m);
                }
                if (lane == 0) cnt_sh[c] = cnt;
            }
            __syncthreads();
            if (tid == 0) {
                int acc = 0;
                #pragma unroll
                for (int i = 0; i < KK; i++) { off_sh[i] = acc; acc += cnt_sh[i]; }
            }
            __syncthreads();
            #pragma unroll
            for (int pass = 0; pass < 2; pass++) {
                int c = wid + pass*8;
                int off = off_sh[c], pos = 0;
                #pragma unroll
                for (int ch = 0; ch < LL/32; ch++) {
                    unsigned m = mrec[pass][ch];
                    if ((m >> lane) & 1u)
                        g_bidxC[b*LL + off + pos + __popc(m & ((1u<<lane)-1u))] = ch*32 + lane;
                    pos += __popc(m);
                }
                if (lane == 0) { g_bcnt[b*KK+c] = cnt_sh[c]; g_boff[b*KK+c] = off; }
            }
            __threadfence();
            __syncthreads();
            if (tid == 0) atomicAdd(&g_bkt_done[b], 1);
        } else if (qt == 9 && b == 0) {
            // fold: M2 = W_ih@Wo, cc = W_ih@bo + b_ih + b_hh
            if (tid < GG) {
                int g = tid;
                float wrow[NHH];
                #pragma unroll
                for (int o = 0; o < NHH; o++) wrow[o] = W_ih[g*NHH+o];
                float cc = b_ih[g] + b_hh[g];
                #pragma unroll
                for (int o = 0; o < NHH; o++) cc += wrow[o] * bo[o];
                g_cc[g] = cc;
                for (int c = 0; c < KK; c++) {
                    float a = 0.f;
                    #pragma unroll
                    for (int o = 0; o < NHH; o++) a += wrow[o] * Wo[o*KK+c];
                    g_M2[g*KK+c] = a;
                }
            }
            __threadfence();
            __syncthreads();
            if (tid == 0) atomicAdd(&g_fold_done, 1);
        }

        // ---- wait for batch-b inputs ----
        if (tid == 0) {
            waitcnt(&g_proj_done[b], 8*(run+1));
            waitcnt(&g_bkt_done[b], run+1);
            waitcnt(&g_fold_done, run+1);
        }
        __syncthreads();
        __threadfence();   // all threads: order subsequent reads after flag

        // ---- att: scores + bucketed softmax + GI ----
        float* S_s   = sm + SOFF_S;
        float* kbuf  = sm + SOFF_KB;
        float* val_s = sm + SOFF_VAL;
        float* x_s   = sm + SOFF_X;
        float* M2_s  = sm + SOFF_M2;
        float* cc_s  = sm + SOFF_CC;
        int*   cnt_s  = (int*)(sm + SOFF_INT);
        int*   off_s  = cnt_s + KK;
        int*   bidx_s = off_s + KK;
        int qbase = qt * 32;

        for (int i = tid; i < LL; i += 256) {
            val_s[i]  = val[b*LL+i];
            bidx_s[i] = g_bidxC[b*LL+i];
        }
        if (tid < KK) { cnt_s[tid] = g_bcnt[b*KK+tid]; off_s[tid] = g_boff[b*KK+tid]; }
        for (int i = tid; i < GG*KK; i += 256) {
            int g = i >> 4, c = i & 15;
            M2_s[g*17+c] = g_M2[i];
        }
        if (tid < GG) cc_s[tid] = g_cc[tid];

        // phase 1: S_tile[32][512] = q_tile @ k^T / sqrt(32)
        int ql4 = tid >> 3, kg = tid & 7;     // 32 q-rows x 8 k-groups
        unsigned long long q2[16];
        {
            const ulonglong2* qp = (const ulonglong2*)(g_q + (size_t)(b*LL + qbase + ql4)*EE);
            #pragma unroll
            for (int i = 0; i < 8; i++) {
                ulonglong2 v = qp[i];
                q2[2*i] = v.x; q2[2*i+1] = v.y;
            }
        }
        unsigned kaddr = (unsigned)__cvta_generic_to_shared(kbuf);
        const float sc = 0.17677669529663687f; // 1/sqrt(32)
        for (int kt = 0; kt < 8; kt++) {
            __syncthreads();
            for (int i = tid; i < 512; i += 256) {  // stage 64x32 k-block
                int r = i >> 3, e4 = (i & 7) * 4;
                float4 v = *(const float4*)(g_k + (size_t)(b*LL + kt*64 + r)*EE + e4);
                *(float4*)&kbuf[r*36 + e4] = v;
            }
            __syncthreads();
            // rows kg+8m (m=0..7): an 8-lane phase reads 8 consecutive rows
            // at stride 36 floats -> conflict-free.
            unsigned long long acc[8];
            #pragma unroll
            for (int m = 0; m < 8; m++) acc[m] = 0ull;
            #pragma unroll
            for (int m = 0; m < 8; m++) {
                unsigned rb = kaddr + (unsigned)((kg + 8*m)*36*4);
                #pragma unroll
                for (int j = 0; j < 8; j++) {
                    unsigned long long hx, hy;
                    asm volatile("ld.shared.v2.u64 {%0, %1}, [%2];"
                                 : "=l"(hx), "=l"(hy) : "r"(rb + j*16));
                    FMA2(acc[m], q2[2*j], hx); FMA2(acc[m], q2[2*j+1], hy);
                }
            }
            float* so = &S_s[ql4*LL + kt*64 + kg];
            #pragma unroll
            for (int m = 0; m < 8; m++) so[8*m] = (f2lo(acc[m])+f2hi(acc[m]))*sc;
        }
        __syncthreads();

        // phase 2: bucketed softmax, THREAD per (ql,c), plain-sum exp.
        for (int task = tid; task < 32*KK; task += 256) {
            int ql = task >> 4, c = task & 15;
            int q = qbase + ql;
            int off = off_s[c], cnt = cnt_s[c];
            float se = 0.f, sv = 0.f;
            for (int i = 0; i < cnt; i++) {
                int   kk = bidx_s[off + i];
                float lg = (kk <= q+1) ? fminf(S_s[ql*LL + kk], 80.f) : 0.f;
                float e  = __expf(lg);
                se += e;
                sv += e * val_s[kk];
            }
            x_s[ql*KK + c] = (cnt > 0) ? sv/se : 0.f;
        }
        __syncthreads();

        // phase 3: GI[b,q,g] = cc[g] + sum_c M2[g][c] * x[q][c]
        for (int o = tid; o < 32*GG; o += 256) {
            int ql = o / GG, g = o - ql*GG;
            float acc = cc_s[g];
            #pragma unroll
            for (int c = 0; c < KK; c++) acc += M2_s[g*17+c] * x_s[ql*KK+c];
            g_GI[((size_t)(b*LL) + qbase + ql)*GG + g] = acc;
        }
        __threadfence();
        __syncthreads();
        if (tid == 0) atomicAdd(&g_attq[b*16 + qt], 1);

    } else {
        // ================= GRU block (batch b), quarter-split ===============
        // 256 threads: thread (u = tid>>2, q = tid&3) computes the quarter-k
        // partials of ALL THREE gate rows for unit u. Weights: 24 u64 = 48
        // regs (fits the 128-reg budget; the half-split's 96 spilled).
        // Cross-quarter sum: shfl.bfly(1) then (2) — intra-warp, barrier-free.
        int b = blk - 128;
        float* h_s  = sm;                 // 64 floats
        float* gi_s = sm + 64;            // 2 * CH*GG floats

        int u = tid >> 2, q = tid & 3;
        unsigned long long wr[8], wz[8], wn[8];
        {
            const ulonglong2* r2 = (const ulonglong2*)(W_hh + (size_t)u*NHH       + q*16);
            const ulonglong2* z2 = (const ulonglong2*)(W_hh + (size_t)(64+u)*NHH  + q*16);
            const ulonglong2* n2 = (const ulonglong2*)(W_hh + (size_t)(128+u)*NHH + q*16);
            #pragma unroll
            for (int i = 0; i < 4; i++) {
                ulonglong2 a = r2[i]; wr[2*i] = a.x; wr[2*i+1] = a.y;
                ulonglong2 c = z2[i]; wz[2*i] = c.x; wz[2*i+1] = c.y;
                ulonglong2 d = n2[i]; wn[2*i] = d.x; wn[2*i+1] = d.y;
            }
        }
        float h_old = 0.f;
        if (tid < NHH) h_s[tid] = 0.f;

        unsigned haddr = (unsigned)__cvta_generic_to_shared(h_s) + q*64;
        unsigned gibase = (unsigned)__cvta_generic_to_shared(gi_s);
        const float* gi_src = g_GI + (size_t)b*LL*GG;
        float* out_b = out + (size_t)b*LL*NHH;

        // wait for qtile 0 of this batch (covers GI chunks 0,1)
        waitcnt(&g_attq[b*16 + 0], run+1);
        __syncthreads();

        // prologue: prefetch chunks 0 and 1 (L2-only: cp.async.cg)
        #pragma unroll
        for (int cpre = 0; cpre < 2; cpre++) {
            #pragma unroll
            for (int i = 0; i < 3; i++) {
                int unit = tid + i*256;               // 768 x 16B per chunk
                asm volatile("cp.async.cg.shared.global [%0], [%1], 16;"
                    :: "r"(gibase + cpre*(CH*GG*4) + unit*16),
                       "l"(gi_src + cpre*CH*GG + unit*4));
            }
            asm volatile("cp.async.commit_group;");
        }
        asm volatile("cp.async.wait_group 1;");
        __syncthreads();

        int qt_ok = 0;
        for (int c = 0; c < NCHUNK; c++) {
            const float* gi = gi_s + (c & 1)*(CH*GG);
            for (int s = 0; s < CH; s++) {
                float gr = gi[s*GG + u], gz = gi[s*GG + 64 + u], gn = gi[s*GG + 128 + u];
                // quarter-matvec: 4x LDS.128 of h-quarter, 24 FMA2
                unsigned long long ar=0ull, az=0ull, an=0ull;
                #pragma unroll
                for (int i = 0; i < 4; i++) {
                    unsigned long long hx, hy;
                    asm volatile("ld.shared.v2.u64 {%0, %1}, [%2];"
                                 : "=l"(hx), "=l"(hy) : "r"(haddr + i*16));
                    FMA2(ar, wr[2*i], hx); FMA2(ar, wr[2*i+1], hy);
                    FMA2(az, wz[2*i], hx); FMA2(az, wz[2*i+1], hy);
                    FMA2(an, wn[2*i], hx); FMA2(an, wn[2*i+1], hy);
                }
                float sr = f2lo(ar)+f2hi(ar);
                float sz = f2lo(az)+f2hi(az);
                float sn = f2lo(an)+f2hi(an);
                sr += __shfl_xor_sync(0xffffffffu, sr, 1);
                sz += __shfl_xor_sync(0xffffffffu, sz, 1);
                sn += __shfl_xor_sync(0xffffffffu, sn, 1);
                sr += __shfl_xor_sync(0xffffffffu, sr, 2);
                sz += __shfl_xor_sync(0xffffffffu, sz, 2);
                sn += __shfl_xor_sync(0xffffffffu, sn, 2);

                // biases pre-folded into GI (cc includes b_ih + b_hh)
                float r = 0.5f * tanh_fast(0.5f * (gr + sr)) + 0.5f;  // sigmoid
                float z = 0.5f * tanh_fast(0.5f * (gz + sz)) + 0.5f;  // sigmoid
                float n = tanh_fast(gn + r*sn);
                float hnew = fmaf(z, h_old - n, n);      // (1-z)n + z*h
                if (q == 0) {
                    h_s[u] = hnew;
                    out_b[(c*CH + s)*NHH + u] = hnew;
                }
                h_old = hnew;
                __syncthreads();
            }
            if (c + 2 < NCHUNK) {
                int qt = (c + 2) >> 1;
                if (qt > qt_ok) { waitcnt(&g_attq[b*16 + qt], run+1); qt_ok = qt; }
                #pragma unroll
                for (int i = 0; i < 3; i++) {
                    int unit = tid + i*256;
                    asm volatile("cp.async.cg.shared.global [%0], [%1], 16;"
                        :: "r"(gibase + (c & 1)*(CH*GG*4) + unit*16),
                           "l"(gi_src + (c+2)*CH*GG + unit*4));
                }
                asm volatile("cp.async.commit_group;");
                asm volatile("cp.async.wait_group 1;");   // chunk c+1 complete
            } else {
                asm volatile("cp.async.wait_group 0;");
            }
            __syncthreads();
        }
    }
}

// -------- launch --------
extern "C" void kernel_launch(void* const* d_in, const int* in_sizes, int n_in,
                              void* d_out, int out_size) {
    const float* ts   = (const float*)d_in[0];
    const float* val  = (const float*)d_in[1];
    const int*   mark = (const int*)  d_in[2];
    const float* npm  = (const float*)d_in[3];
    const float* Wl   = (const float*)d_in[4];
    const float* bl   = (const float*)d_in[5];
    const float* Wp   = (const float*)d_in[6];
    const float* bp   = (const float*)d_in[7];
    const float* Wq   = (const float*)d_in[8];
    const float* bq   = (const float*)d_in[9];
    const float* Wk   = (const float*)d_in[10];
    const float* bk   = (const float*)d_in[11];
    const float* Wo   = (const float*)d_in[12];
    const float* bo   = (const float*)d_in[13];
    const float* W_ih = (const float*)d_in[14];
    const float* W_hh = (const float*)d_in[15];
    const float* b_ih = (const float*)d_in[16];
    const float* b_hh = (const float*)d_in[17];
    float* out = (float*)d_out;

    static int attr_set = 0;
    if (!attr_set) {
        cudaFuncSetAttribute(k_all, cudaFuncAttributeMaxDynamicSharedMemorySize,
                             SMEM_BYTES);
        attr_set = 1;
    }

    k_all<<<NBLK, 256, SMEM_BYTES>>>(ts, val, mark, npm, Wl, bl, Wp, bp,
                                     Wq, bq, Wk, bk, Wo, bo,
                                     W_ih, W_hh, b_ih, b_hh, out);
}

// round 13
// speedup vs baseline: 1.2197x; 1.2197x over previous
#include <cuda_runtime.h>
#include <math.h>

#define BB  8
#define LL  512
#define KK  16
#define EE  32
#define NHH 64
#define GG  192
#define CH      16           // GRU: steps per GI prefetch chunk
#define NCHUNK  (LL/CH)      // 32

// -------- scratch: ONLY the GI handoff buffer (no other globals) ----------
__device__ float g_GI[BB*LL*GG];     // input gates (Wo/W_ih folded, + b-folds)

__device__ __forceinline__ float tanh_fast(float x) {
    float y;
    asm("tanh.approx.f32 %0, %1;" : "=f"(y) : "f"(x));
    return y;
}
#define FMA2(acc, x, y) \
    asm("fma.rn.f32x2 %0, %1, %2, %0;" : "+l"(acc) : "l"(x), "l"(y))
__device__ __forceinline__ float f2lo(unsigned long long v) {
    return __uint_as_float((unsigned)v);
}
__device__ __forceinline__ float f2hi(unsigned long long v) {
    return __uint_as_float((unsigned)(v >> 32));
}

// smem layout (floats) — att kernel
#define A_S    0        // 32*512 score tile
#define A_KEB  16384    // 64*33 key-embedding tile
#define A_KB   18496    // 64*36 projected k/q tile (16B-aligned rows)
#define A_WQ   20800    // 32*33
#define A_WK   21856    // 32*33
#define A_VAL  22912    // 512
#define A_X    23424    // 512
#define A_M2   23936    // 192*17
#define A_CC   27200    // 192
#define A_INT  27392    // ints: cnt 16, off 16, bidx 512
#define A_MISC 27936    // sWp 32, sbp 32, sWl/sbl 2
#define SM_FLOATS (A_MISC + 66)
#define SM_BYTES  (SM_FLOATS * 4)

// ============ kernel 1: SELF-CONTAINED attention block (qt, b) =============
// Each block redundantly computes its own key-embeddings, projections,
// buckets, and folded matrices in smem. No cross-block dependencies at all.
// Only output: g_GI.
__global__ void __launch_bounds__(256) k_att(
        const float* __restrict__ ts,   const float* __restrict__ val,
        const int*   __restrict__ mark, const float* __restrict__ npm,
        const float* __restrict__ Wl, const float* __restrict__ bl,
        const float* __restrict__ Wp, const float* __restrict__ bp,
        const float* __restrict__ Wq, const float* __restrict__ bq,
        const float* __restrict__ Wk, const float* __restrict__ bk,
        const float* __restrict__ Wo, const float* __restrict__ bo,
        const float* __restrict__ W_ih, const float* __restrict__ b_ih) {
    extern __shared__ float sm[];
    float* S_s   = sm + A_S;
    float* keb   = sm + A_KEB;
    float* kb    = sm + A_KB;
    float* wq_s  = sm + A_WQ;
    float* wk_s  = sm + A_WK;
    float* val_s = sm + A_VAL;
    float* x_s   = sm + A_X;
    float* M2_s  = sm + A_M2;
    float* cc_s  = sm + A_CC;
    int*   cnt_s  = (int*)(sm + A_INT);
    int*   off_s  = cnt_s + KK;
    int*   bidx_s = off_s + KK;
    float* sWp  = sm + A_MISC;
    float* sbp  = sWp + EE;
    float* sWls = sbp + EE;

    int blk = blockIdx.x, tid = threadIdx.x;
    int qt = blk >> 3, b = blk & 7;        // 16 qtiles x 8 batches
    int qbase = qt * 32;
    int wid = tid >> 5, lane = tid & 31;

    // ---- stage 1: weights/val staging + M2 fold + bucket ballots ----
    for (int i = tid; i < EE*EE; i += 256) {
        int e = i >> 5, j = i & 31;
        wq_s[e*33+j] = Wq[i];
        wk_s[e*33+j] = Wk[i];
    }
    if (tid < EE-1) { sWp[tid] = Wp[tid]; sbp[tid] = bp[tid]; }
    if (tid == 0)   { sWls[0] = Wl[0]; sWls[1] = bl[0]; }
    for (int i = tid; i < LL; i += 256) val_s[i] = val[b*LL+i];

    // M2 = W_ih@Wo, cc = W_ih@bo + b_ih  (tid < 192)
    if (tid < GG) {
        int g = tid;
        float wrow[NHH];
        #pragma unroll
        for (int o = 0; o < NHH; o++) wrow[o] = __ldg(&W_ih[g*NHH+o]);
        float cc = __ldg(&b_ih[g]);
        #pragma unroll
        for (int o = 0; o < NHH; o++) cc += wrow[o] * __ldg(&bo[o]);
        cc_s[g] = cc;
        for (int c = 0; c < KK; c++) {
            float a = 0.f;
            #pragma unroll
            for (int o = 0; o < NHH; o++) a += wrow[o] * __ldg(&Wo[o*KK+c]);
            M2_s[g*17+c] = a;
        }
    }

    // bucket ballots: 8 warps x 2 categories each
    __shared__ int cnt_sh[KK], off_sh[KK];
    unsigned mrec[2][LL/32];
    #pragma unroll
    for (int pass = 0; pass < 2; pass++) {
        int c = wid + pass*8;
        int cnt = 0;
        #pragma unroll
        for (int ch = 0; ch < LL/32; ch++) {
            int k = ch*32 + lane;
            int   mk = mark[b*LL+k];
            float np = npm[b*LL+k];
            bool hit = (mk == c+1) && (np > 0.f);
            unsigned m = __ballot_sync(0xffffffffu, hit);
            mrec[pass][ch] = m;
            cnt += __popc(m);
        }
        if (lane == 0) cnt_sh[c] = cnt;
    }
    __syncthreads();

    // ---- stage 2: bucket scan (tid0) + q-tile key-embedding ----
    if (tid == 0) {
        int acc = 0;
        #pragma unroll
        for (int i = 0; i < KK; i++) { off_sh[i] = acc; acc += cnt_sh[i]; }
    }
    // ke for the 32 q-rows into keb
    for (int idx = tid; idx < 32*EE; idx += 256) {
        int r = idx >> 5, i = idx & 31;
        float t = ts[b*LL + qbase + r];
        keb[r*33 + i] = (i == 0) ? fmaf(t, sWls[0], sWls[1])
                                 : __sinf(fmaf(t, sWp[i-1], sbp[i-1]));
    }
    // per-thread weight columns (registers)
    int e = lane;
    float wq[EE], wk[EE];
    #pragma unroll
    for (int j = 0; j < EE; j++) { wq[j] = wq_s[e*33+j]; wk[j] = wk_s[e*33+j]; }
    float bqv = __ldg(&bq[e]), bkv = __ldg(&bk[e]);
    __syncthreads();

    // ---- stage 3: bucket compaction + q projection into kb rows 0..31 ----
    #pragma unroll
    for (int pass = 0; pass < 2; pass++) {
        int c = wid + pass*8;
        int off = off_sh[c], pos = 0;
        #pragma unroll
        for (int ch = 0; ch < LL/32; ch++) {
            unsigned m = mrec[pass][ch];
            if ((m >> lane) & 1u)
                bidx_s[off + pos + __popc(m & ((1u<<lane)-1u))] = ch*32 + lane;
            pos += __popc(m);
        }
        if (lane == 0) { cnt_s[c] = cnt_sh[c]; off_s[c] = off; }
    }
    #pragma unroll
    for (int p = 0; p < 4; p++) {            // 8 warps x 4 rows = 32 q-rows
        int r = wid*4 + p;
        float aq = bqv;
        #pragma unroll
        for (int j = 0; j < EE; j++) aq = fmaf(wq[j], keb[r*33+j], aq);
        kb[r*36 + e] = aq;
    }
    __syncthreads();

    // ---- stage 4: q2 registers (broadcast reads of kb) ----
    int ql4 = tid >> 3, kg = tid & 7;        // 32 q-rows x 8 k-groups
    unsigned kaddr = (unsigned)__cvta_generic_to_shared(kb);
    unsigned long long q2[16];
    {
        unsigned qrow = kaddr + (unsigned)(ql4*36*4);
        #pragma unroll
        for (int i = 0; i < 8; i++) {
            asm volatile("ld.shared.v2.u64 {%0, %1}, [%2];"
                         : "=l"(q2[2*i]), "=l"(q2[2*i+1]) : "r"(qrow + i*16));
        }
    }
    __syncthreads();

    // ---- stage 5: fused (ke -> k-proj -> GEMM) over 8 k-tiles ----
    const float sc = 0.17677669529663687f;   // 1/sqrt(32)
    for (int kt = 0; kt < 8; kt++) {
        // ke for k-rows kt*64..+63
        for (int idx = tid; idx < 64*EE; idx += 256) {
            int r = idx >> 5, i = idx & 31;
            float t = ts[b*LL + kt*64 + r];
            keb[r*33 + i] = (i == 0) ? fmaf(t, sWls[0], sWls[1])
                                     : __sinf(fmaf(t, sWp[i-1], sbp[i-1]));
        }
        __syncthreads();
        // k projection into kb (64 rows): thread (e, wid) rows wid*8+p
        #pragma unroll
        for (int p = 0; p < 8; p++) {
            int r = wid*8 + p;
            float ak = bkv;
            #pragma unroll
            for (int j = 0; j < EE; j++) ak = fmaf(wk[j], keb[r*33+j], ak);
            kb[r*36 + e] = ak;
        }
        __syncthreads();
        // GEMM: rows kg+8m (conflict-free at stride 36)
        unsigned long long acc[8];
        #pragma unroll
        for (int m = 0; m < 8; m++) acc[m] = 0ull;
        #pragma unroll
        for (int m = 0; m < 8; m++) {
            unsigned rb = kaddr + (unsigned)((kg + 8*m)*36*4);
            #pragma unroll
            for (int j = 0; j < 8; j++) {
                unsigned long long hx, hy;
                asm volatile("ld.shared.v2.u64 {%0, %1}, [%2];"
                             : "=l"(hx), "=l"(hy) : "r"(rb + j*16));
                FMA2(acc[m], q2[2*j], hx); FMA2(acc[m], q2[2*j+1], hy);
            }
        }
        float* so = &S_s[ql4*LL + kt*64 + kg];
        #pragma unroll
        for (int m = 0; m < 8; m++) so[8*m] = (f2lo(acc[m])+f2hi(acc[m]))*sc;
        __syncthreads();
    }

    // ---- stage 6: bucketed softmax, THREAD per (ql,c), plain-sum exp ----
    // logits bounded; sum-of-exp == softmax exactly; clamp@80 guards overflow.
    for (int task = tid; task < 32*KK; task += 256) {
        int ql = task >> 4, c = task & 15;
        int q = qbase + ql;
        int off = off_s[c], cnt = cnt_s[c];
        float se = 0.f, sv = 0.f;
        for (int i = 0; i < cnt; i++) {
            int   kk = bidx_s[off + i];
            float lg = (kk <= q+1) ? fminf(S_s[ql*LL + kk], 80.f) : 0.f;
            float ex = __expf(lg);
            se += ex;
            sv += ex * val_s[kk];
        }
        x_s[ql*KK + c] = (cnt > 0) ? sv/se : 0.f;
    }
    __syncthreads();

    // ---- stage 7: GI[b,q,g] = cc[g] + sum_c M2[g][c] * x[q][c] ----
    for (int o = tid; o < 32*GG; o += 256) {
        int ql = o / GG, g = o - ql*GG;
        float acc = cc_s[g];
        #pragma unroll
        for (int c = 0; c < KK; c++) acc += M2_s[g*17+c] * x_s[ql*KK+c];
        g_GI[((size_t)(b*LL) + qbase + ql)*GG + g] = acc;
    }
}

// ============ kernel 2: GRU scan (round-8 proven design) ===================
// 128 threads = 4 warps. thread (u = tid>>1, half = tid&1) computes the
// half-k partial of ALL THREE gate rows; cross-half sum via shfl.bfly(1).
// One __syncthreads per step. GI double-buffered via cp.async.
__global__ void __launch_bounds__(128) k_gru(const float* __restrict__ W_hh,
                                             const float* __restrict__ b_hh,
                                             float* __restrict__ out) {
    int b = blockIdx.x, tid = threadIdx.x;
    int u = tid >> 1, half = tid & 1;
    __shared__ __align__(16) float h_s[NHH];
    __shared__ __align__(16) float gi_s[2][CH*GG];

    // weights: rows u / 64+u / 128+u, k-slice [half*32,+32), packed f32x2
    unsigned long long wr[16], wz[16], wn[16];
    {
        const ulonglong2* r2 = (const ulonglong2*)(W_hh + (size_t)u*NHH       + half*32);
        const ulonglong2* z2 = (const ulonglong2*)(W_hh + (size_t)(64+u)*NHH  + half*32);
        const ulonglong2* n2 = (const ulonglong2*)(W_hh + (size_t)(128+u)*NHH + half*32);
        #pragma unroll
        for (int i = 0; i < 8; i++) {
            ulonglong2 a = r2[i]; wr[2*i] = a.x; wr[2*i+1] = a.y;
            ulonglong2 c = z2[i]; wz[2*i] = c.x; wz[2*i+1] = c.y;
            ulonglong2 d = n2[i]; wn[2*i] = d.x; wn[2*i+1] = d.y;
        }
    }
    float br = b_hh[u], bz = b_hh[64+u], bn = b_hh[128+u];
    float h_old = 0.f;
    if (tid < NHH) h_s[tid] = 0.f;

    unsigned haddr = (unsigned)__cvta_generic_to_shared(h_s) + half*128;
    unsigned gibase = (unsigned)__cvta_generic_to_shared(gi_s);
    const float* gi_src = g_GI + (size_t)b*LL*GG;
    float* out_b = out + (size_t)b*LL*NHH;

    // prologue: prefetch chunks 0 and 1
    #pragma unroll
    for (int cpre = 0; cpre < 2; cpre++) {
        #pragma unroll
        for (int i = 0; i < 6; i++) {
            int unit = tid + i*128;               // 768 x 16B per chunk
            asm volatile("cp.async.ca.shared.global [%0], [%1], 16;"
                :: "r"(gibase + cpre*(CH*GG*4) + unit*16),
                   "l"(gi_src + cpre*CH*GG + unit*4));
        }
        asm volatile("cp.async.commit_group;");
    }
    asm volatile("cp.async.wait_group 1;");
    __syncthreads();

    for (int c = 0; c < NCHUNK; c++) {
        const float* gi = (const float*)gi_s[c & 1];
        for (int s = 0; s < CH; s++) {
            // gate inputs first (LDS latency overlaps with matvec)
            float gr = gi[s*GG + u], gz = gi[s*GG + 64 + u], gn = gi[s*GG + 128 + u];
            // half-matvec: 8x LDS.128 of h-half, 48 FMA2 over 6 chains
            unsigned long long ar0=0ull, ar1=0ull, az0=0ull, az1=0ull,
                               an0=0ull, an1=0ull;
            #pragma unroll
            for (int i = 0; i < 8; i++) {
                unsigned long long hx, hy;
                asm volatile("ld.shared.v2.u64 {%0, %1}, [%2];"
                             : "=l"(hx), "=l"(hy) : "r"(haddr + i*16));
                FMA2(ar0, wr[2*i], hx); FMA2(ar1, wr[2*i+1], hy);
                FMA2(az0, wz[2*i], hx); FMA2(az1, wz[2*i+1], hy);
                FMA2(an0, wn[2*i], hx); FMA2(an1, wn[2*i+1], hy);
            }
            float sr = (f2lo(ar0)+f2hi(ar0)) + (f2lo(ar1)+f2hi(ar1));
            float sz = (f2lo(az0)+f2hi(az0)) + (f2lo(az1)+f2hi(az1));
            float sn = (f2lo(an0)+f2hi(an0)) + (f2lo(an1)+f2hi(an1));
            sr += __shfl_xor_sync(0xffffffffu, sr, 1);
            sz += __shfl_xor_sync(0xffffffffu, sz, 1);
            sn += __shfl_xor_sync(0xffffffffu, sn, 1);

            // reference: n = tanh(inn + r*(W_n.h + b_hh_n)) — bn INSIDE r*()
            float r = 0.5f * tanh_fast(0.5f * (gr + sr + br)) + 0.5f;  // sigmoid
            float z = 0.5f * tanh_fast(0.5f * (gz + sz + bz)) + 0.5f;  // sigmoid
            float n = tanh_fast(gn + r*(sn + bn));
            float hnew = fmaf(z, h_old - n, n);      // (1-z)n + z*h
            h_s[u] = hnew;                            // both halves, same value
            if (half == 0) out_b[(c*CH + s)*NHH + u] = hnew;
            h_old = hnew;
            __syncthreads();
        }
        // staged GI prefetch for chunk c+2 into the buffer just consumed
        if (c + 2 < NCHUNK) {
            #pragma unroll
            for (int i = 0; i < 6; i++) {
                int unit = tid + i*128;
                asm volatile("cp.async.ca.shared.global [%0], [%1], 16;"
                    :: "r"(gibase + (c & 1)*(CH*GG*4) + unit*16),
                       "l"(gi_src + (c+2)*CH*GG + unit*4));
            }
            asm volatile("cp.async.commit_group;");
            asm volatile("cp.async.wait_group 1;");   // chunk c+1 complete
        } else {
            asm volatile("cp.async.wait_group 0;");
        }
        __syncthreads();
    }
}

// -------- launch --------
extern "C" void kernel_launch(void* const* d_in, const int* in_sizes, int n_in,
                              void* d_out, int out_size) {
    const float* ts   = (const float*)d_in[0];
    const float* val  = (const float*)d_in[1];
    const int*   mark = (const int*)  d_in[2];
    const float* npm  = (const float*)d_in[3];
    const float* Wl   = (const float*)d_in[4];
    const float* bl   = (const float*)d_in[5];
    const float* Wp   = (const float*)d_in[6];
    const float* bp   = (const float*)d_in[7];
    const float* Wq   = (const float*)d_in[8];
    const float* bq   = (const float*)d_in[9];
    const float* Wk   = (const float*)d_in[10];
    const float* bk   = (const float*)d_in[11];
    const float* Wo   = (const float*)d_in[12];
    const float* bo   = (const float*)d_in[13];
    const float* W_ih = (const float*)d_in[14];
    const float* W_hh = (const float*)d_in[15];
    const float* b_ih = (const float*)d_in[16];
    const float* b_hh = (const float*)d_in[17];
    float* out = (float*)d_out;

    cudaFuncSetAttribute(k_att, cudaFuncAttributeMaxDynamicSharedMemorySize,
                         SM_BYTES);

    k_att<<<128, 256, SM_BYTES>>>(ts, val, mark, npm, Wl, bl, Wp, bp,
                                  Wq, bq, Wk, bk, Wo, bo, W_ih, b_ih);
    k_gru<<<8, 128>>>(W_hh, b_hh, out);
}

// round 14
// speedup vs baseline: 1.2850x; 1.0536x over previous
#include <cuda_runtime.h>
#include <math.h>

#define BB  8
#define LL  512
#define KK  16
#define EE  32
#define NHH 64
#define GG  192
#define CH      16           // GRU: steps per GI prefetch chunk
#define NCHUNK  (LL/CH)      // 32

// -------- scratch: ONLY the GI handoff buffer (no other globals) ----------
__device__ float g_GI[BB*LL*GG];     // input gates (Wo/W_ih folded)

__device__ __forceinline__ float tanh_fast(float x) {
    float y;
    asm("tanh.approx.f32 %0, %1;" : "=f"(y) : "f"(x));
    return y;
}
#define FMA2(acc, x, y) \
    asm("fma.rn.f32x2 %0, %1, %2, %0;" : "+l"(acc) : "l"(x), "l"(y))
#define ADDF2(out, a, b) \
    asm("add.rn.f32x2 %0, %1, %2;" : "=l"(out) : "l"(a), "l"(b))
__device__ __forceinline__ float f2lo(unsigned long long v) {
    return __uint_as_float((unsigned)v);
}
__device__ __forceinline__ float f2hi(unsigned long long v) {
    return __uint_as_float((unsigned)(v >> 32));
}

// smem layout (floats) — att kernel
#define A_S    0        // 32*512 score tile
#define A_KEB  16384    // 64*33 key-embedding tile
#define A_KB   18496    // 64*36 projected k/q tile (16B-aligned rows)
#define A_WQ   20800    // 32*33
#define A_WK   21856    // 32*33
#define A_VAL  22912    // 512
#define A_X    23424    // 512
#define A_M2   23936    // 192*17
#define A_CC   27200    // 192
#define A_INT  27392    // ints: cnt 16, off 16, bidx 512
#define A_MISC 27936    // sWp 32, sbp 32, sWl/sbl 2
#define A_WO   28004    // 1024 floats, 16B-aligned (Wo staged)
#define A_BO   29028    // 64 floats
#define SM_FLOATS (A_BO + 64)
#define SM_BYTES  (SM_FLOATS * 4)

// ============ kernel 1: SELF-CONTAINED attention block (qt, b) =============
__global__ void __launch_bounds__(256) k_att(
        const float* __restrict__ ts,   const float* __restrict__ val,
        const int*   __restrict__ mark, const float* __restrict__ npm,
        const float* __restrict__ Wl, const float* __restrict__ bl,
        const float* __restrict__ Wp, const float* __restrict__ bp,
        const float* __restrict__ Wq, const float* __restrict__ bq,
        const float* __restrict__ Wk, const float* __restrict__ bk,
        const float* __restrict__ Wo, const float* __restrict__ bo,
        const float* __restrict__ W_ih, const float* __restrict__ b_ih) {
    extern __shared__ float sm[];
    float* S_s   = sm + A_S;
    float* keb   = sm + A_KEB;
    float* kb    = sm + A_KB;
    float* wq_s  = sm + A_WQ;
    float* wk_s  = sm + A_WK;
    float* val_s = sm + A_VAL;
    float* x_s   = sm + A_X;
    float* M2_s  = sm + A_M2;
    float* cc_s  = sm + A_CC;
    int*   cnt_s  = (int*)(sm + A_INT);
    int*   off_s  = cnt_s + KK;
    int*   bidx_s = off_s + KK;
    float* sWp  = sm + A_MISC;
    float* sbp  = sWp + EE;
    float* sWls = sbp + EE;
    float* wo_s = sm + A_WO;
    float* bo_s = sm + A_BO;

    int blk = blockIdx.x, tid = threadIdx.x;
    int qt = blk >> 3, b = blk & 7;        // 16 qtiles x 8 batches
    int qbase = qt * 32;
    int wid = tid >> 5, lane = tid & 31;
    unsigned smbase = (unsigned)__cvta_generic_to_shared(sm);

    // ---- stage 1: staging + bucket ballots ----
    for (int i = tid; i < EE*EE; i += 256) {
        int e = i >> 5, j = i & 31;
        wq_s[e*33+j] = Wq[i];
        wk_s[e*33+j] = Wk[i];
    }
    if (tid < EE-1) { sWp[tid] = Wp[tid]; sbp[tid] = bp[tid]; }
    if (tid == 0)   { sWls[0] = Wl[0]; sWls[1] = bl[0]; }
    for (int i = tid; i < LL; i += 256) val_s[i] = val[b*LL+i];
    // stage Wo (64x16 floats) coalesced + bo
    ((float4*)wo_s)[tid] = __ldg(&((const float4*)Wo)[tid]);
    if (tid < NHH) bo_s[tid] = __ldg(&bo[tid]);

    // bucket ballots: 8 warps x 2 categories each (register-local)
    __shared__ int cnt_sh[KK], off_sh[KK];
    unsigned mrec[2][LL/32];
    #pragma unroll
    for (int pass = 0; pass < 2; pass++) {
        int c = wid + pass*8;
        int cnt = 0;
        #pragma unroll
        for (int ch = 0; ch < LL/32; ch++) {
            int k = ch*32 + lane;
            int   mk = mark[b*LL+k];
            float np = npm[b*LL+k];
            bool hit = (mk == c+1) && (np > 0.f);
            unsigned m = __ballot_sync(0xffffffffu, hit);
            mrec[pass][ch] = m;
            cnt += __popc(m);
        }
        if (lane == 0) cnt_sh[c] = cnt;
    }
    __syncthreads();

    // ---- stage 2: M2 fold (smem Wo, FMA2) + scan + q-tile key-embedding ----
    if (tid < GG) {
        int g = tid;
        float wrow[NHH];
        const float4* wih4 = (const float4*)(W_ih + (size_t)g*NHH);
        #pragma unroll
        for (int i = 0; i < 16; i++) {
            float4 v = __ldg(&wih4[i]);
            wrow[4*i]   = v.x; wrow[4*i+1] = v.y;
            wrow[4*i+2] = v.z; wrow[4*i+3] = v.w;
        }
        float cc = __ldg(&b_ih[g]);
        unsigned long long acc2[8];
        #pragma unroll
        for (int j = 0; j < 8; j++) acc2[j] = 0ull;
        unsigned woaddr = smbase + A_WO*4;
        #pragma unroll 8
        for (int o = 0; o < NHH; o++) {
            float w = wrow[o];
            cc = fmaf(w, bo_s[o], cc);
            unsigned long long wp;
            asm("mov.b64 %0, {%1, %1};" : "=l"(wp) : "r"(__float_as_uint(w)));
            unsigned ab = woaddr + (unsigned)(o*64);
            #pragma unroll
            for (int j2 = 0; j2 < 4; j2++) {
                unsigned long long x, y;
                asm volatile("ld.shared.v2.u64 {%0, %1}, [%2];"
                             : "=l"(x), "=l"(y) : "r"(ab + j2*16));
                FMA2(acc2[2*j2],   wp, x);
                FMA2(acc2[2*j2+1], wp, y);
            }
        }
        cc_s[g] = cc;
        #pragma unroll
        for (int j = 0; j < 8; j++) {
            M2_s[g*17 + 2*j]   = f2lo(acc2[j]);
            M2_s[g*17 + 2*j+1] = f2hi(acc2[j]);
        }
    }
    if (tid == 0) {
        int acc = 0;
        #pragma unroll
        for (int i = 0; i < KK; i++) { off_sh[i] = acc; acc += cnt_sh[i]; }
    }
    // ke for the 32 q-rows into keb
    for (int idx = tid; idx < 32*EE; idx += 256) {
        int r = idx >> 5, i = idx & 31;
        float t = ts[b*LL + qbase + r];
        keb[r*33 + i] = (i == 0) ? fmaf(t, sWls[0], sWls[1])
                                 : __sinf(fmaf(t, sWp[i-1], sbp[i-1]));
    }
    // per-thread weight columns (registers)
    int e = lane;
    float wq[EE], wk[EE];
    #pragma unroll
    for (int j = 0; j < EE; j++) { wq[j] = wq_s[e*33+j]; wk[j] = wk_s[e*33+j]; }
    float bqv = __ldg(&bq[e]), bkv = __ldg(&bk[e]);
    __syncthreads();

    // ---- stage 3: bucket compaction + q projection into kb rows 0..31 ----
    #pragma unroll
    for (int pass = 0; pass < 2; pass++) {
        int c = wid + pass*8;
        int off = off_sh[c], pos = 0;
        #pragma unroll
        for (int ch = 0; ch < LL/32; ch++) {
            unsigned m = mrec[pass][ch];
            if ((m >> lane) & 1u)
                bidx_s[off + pos + __popc(m & ((1u<<lane)-1u))] = ch*32 + lane;
            pos += __popc(m);
        }
        if (lane == 0) { cnt_s[c] = cnt_sh[c]; off_s[c] = off; }
    }
    #pragma unroll
    for (int p = 0; p < 4; p++) {            // 8 warps x 4 rows = 32 q-rows
        int r = wid*4 + p;
        float aq = bqv;
        #pragma unroll
        for (int j = 0; j < EE; j++) aq = fmaf(wq[j], keb[r*33+j], aq);
        kb[r*36 + e] = aq;
    }
    __syncthreads();

    // ---- stage 4: q2 registers (broadcast reads of kb) ----
    int ql4 = tid >> 3, kg = tid & 7;        // 32 q-rows x 8 k-groups
    unsigned kaddr = smbase + A_KB*4;
    unsigned long long q2[16];
    {
        unsigned qrow = kaddr + (unsigned)(ql4*36*4);
        #pragma unroll
        for (int i = 0; i < 8; i++) {
            asm volatile("ld.shared.v2.u64 {%0, %1}, [%2];"
                         : "=l"(q2[2*i]), "=l"(q2[2*i+1]) : "r"(qrow + i*16));
        }
    }
    __syncthreads();

    // ---- stage 5: fused (ke -> k-proj -> GEMM) over 8 k-tiles ----
    const float sc = 0.17677669529663687f;   // 1/sqrt(32)
    for (int kt = 0; kt < 8; kt++) {
        for (int idx = tid; idx < 64*EE; idx += 256) {
            int r = idx >> 5, i = idx & 31;
            float t = ts[b*LL + kt*64 + r];
            keb[r*33 + i] = (i == 0) ? fmaf(t, sWls[0], sWls[1])
                                     : __sinf(fmaf(t, sWp[i-1], sbp[i-1]));
        }
        __syncthreads();
        #pragma unroll
        for (int p = 0; p < 8; p++) {
            int r = wid*8 + p;
            float ak = bkv;
            #pragma unroll
            for (int j = 0; j < EE; j++) ak = fmaf(wk[j], keb[r*33+j], ak);
            kb[r*36 + e] = ak;
        }
        __syncthreads();
        // GEMM: rows kg+8m (conflict-free at stride 36)
        unsigned long long acc[8];
        #pragma unroll
        for (int m = 0; m < 8; m++) acc[m] = 0ull;
        #pragma unroll
        for (int m = 0; m < 8; m++) {
            unsigned rb = kaddr + (unsigned)((kg + 8*m)*36*4);
            #pragma unroll
            for (int j = 0; j < 8; j++) {
                unsigned long long hx, hy;
                asm volatile("ld.shared.v2.u64 {%0, %1}, [%2];"
                             : "=l"(hx), "=l"(hy) : "r"(rb + j*16));
                FMA2(acc[m], q2[2*j], hx); FMA2(acc[m], q2[2*j+1], hy);
            }
        }
        float* so = &S_s[ql4*LL + kt*64 + kg];
        #pragma unroll
        for (int m = 0; m < 8; m++) so[8*m] = (f2lo(acc[m])+f2hi(acc[m]))*sc;
        __syncthreads();
    }

    // ---- stage 6: bucketed softmax, THREAD per (ql,c), plain-sum exp ----
    for (int task = tid; task < 32*KK; task += 256) {
        int ql = task >> 4, c = task & 15;
        int q = qbase + ql;
        int off = off_s[c], cnt = cnt_s[c];
        float se = 0.f, sv = 0.f;
        for (int i = 0; i < cnt; i++) {
            int   kk = bidx_s[off + i];
            float lg = (kk <= q+1) ? fminf(S_s[ql*LL + kk], 80.f) : 0.f;
            float ex = __expf(lg);
            se += ex;
            sv += ex * val_s[kk];
        }
        x_s[ql*KK + c] = (cnt > 0) ? sv/se : 0.f;
    }
    __syncthreads();

    // ---- stage 7: GI[b,q,g] = cc[g] + sum_c M2[g][c] * x[q][c] ----
    for (int o = tid; o < 32*GG; o += 256) {
        int ql = o / GG, g = o - ql*GG;
        float acc = cc_s[g];
        #pragma unroll
        for (int c = 0; c < KK; c++) acc += M2_s[g*17+c] * x_s[ql*KK+c];
        g_GI[((size_t)(b*LL) + qbase + ql)*GG + g] = acc;
    }
}

// ============ kernel 2: GRU scan (half-split + shfl, trimmed chain) ========
__global__ void __launch_bounds__(128) k_gru(const float* __restrict__ W_hh,
                                             const float* __restrict__ b_hh,
                                             float* __restrict__ out) {
    int b = blockIdx.x, tid = threadIdx.x;
    int u = tid >> 1, half = tid & 1;
    __shared__ __align__(16) float h_s[NHH];
    __shared__ __align__(16) float gi_s[2][CH*GG];

    // weights: rows u / 64+u / 128+u, k-slice [half*32,+32), packed f32x2
    unsigned long long wr[16], wz[16], wn[16];
    {
        const ulonglong2* r2 = (const ulonglong2*)(W_hh + (size_t)u*NHH       + half*32);
        const ulonglong2* z2 = (const ulonglong2*)(W_hh + (size_t)(64+u)*NHH  + half*32);
        const ulonglong2* n2 = (const ulonglong2*)(W_hh + (size_t)(128+u)*NHH + half*32);
        #pragma unroll
        for (int i = 0; i < 8; i++) {
            ulonglong2 a = r2[i]; wr[2*i] = a.x; wr[2*i+1] = a.y;
            ulonglong2 c = z2[i]; wz[2*i] = c.x; wz[2*i+1] = c.y;
            ulonglong2 d = n2[i]; wn[2*i] = d.x; wn[2*i+1] = d.y;
        }
    }
    float br = b_hh[u], bz = b_hh[64+u], bn = b_hh[128+u];
    float h_old = 0.f;
    if (tid < NHH) h_s[tid] = 0.f;

    unsigned haddr = (unsigned)__cvta_generic_to_shared(h_s) + half*128;
    unsigned gibase = (unsigned)__cvta_generic_to_shared(gi_s);
    const float* gi_src = g_GI + (size_t)b*LL*GG;
    float* out_b = out + (size_t)b*LL*NHH;

    // prologue: prefetch chunks 0 and 1
    #pragma unroll
    for (int cpre = 0; cpre < 2; cpre++) {
        #pragma unroll
        for (int i = 0; i < 6; i++) {
            int unit = tid + i*128;               // 768 x 16B per chunk
            asm volatile("cp.async.ca.shared.global [%0], [%1], 16;"
                :: "r"(gibase + cpre*(CH*GG*4) + unit*16),
                   "l"(gi_src + cpre*CH*GG + unit*4));
        }
        asm volatile("cp.async.commit_group;");
    }
    asm volatile("cp.async.wait_group 1;");
    __syncthreads();

    for (int c = 0; c < NCHUNK; c++) {
        const float* gi = (const float*)gi_s[c & 1];
        #pragma unroll 4
        for (int s = 0; s < CH; s++) {
            // gate inputs first (LDS latency overlaps with matvec)
            float gr = gi[s*GG + u], gz = gi[s*GG + 64 + u], gn = gi[s*GG + 128 + u];
            // half-matvec: 8x LDS.128 of h-half, 48 FMA2 over 6 chains
            unsigned long long ar0=0ull, ar1=0ull, az0=0ull, az1=0ull,
                               an0=0ull, an1=0ull;
            #pragma unroll
            for (int i = 0; i < 8; i++) {
                unsigned long long hx, hy;
                asm volatile("ld.shared.v2.u64 {%0, %1}, [%2];"
                             : "=l"(hx), "=l"(hy) : "r"(haddr + i*16));
                FMA2(ar0, wr[2*i], hx); FMA2(ar1, wr[2*i+1], hy);
                FMA2(az0, wz[2*i], hx); FMA2(az1, wz[2*i+1], hy);
                FMA2(an0, wn[2*i], hx); FMA2(an1, wn[2*i+1], hy);
            }
            unsigned long long arT, azT, anT;
            ADDF2(arT, ar0, ar1);
            ADDF2(azT, az0, az1);
            ADDF2(anT, an0, an1);
            float sr = f2lo(arT) + f2hi(arT);
            float sz = f2lo(azT) + f2hi(azT);
            float sn = f2lo(anT) + f2hi(anT);
            sr += __shfl_xor_sync(0xffffffffu, sr, 1);
            sz += __shfl_xor_sync(0xffffffffu, sz, 1);
            sn += __shfl_xor_sync(0xffffffffu, sn, 1);

            // r = sigmoid(gr+sr+br) = 0.5*tanh(0.5*(..))+0.5
            // n = tanh(gn + r*(sn+bn)) = tanh(fma(0.5*snb, t_r, gn+0.5*snb))
            float snb  = sn + bn;
            float hsn  = 0.5f * snb;
            float base = gn + hsn;
            float t_r  = tanh_fast(0.5f * (gr + sr + br));
            float t_z  = tanh_fast(0.5f * (gz + sz + bz));
            float n    = tanh_fast(fmaf(hsn, t_r, base));
            float z    = fmaf(0.5f, t_z, 0.5f);
            float hnew = fmaf(z, h_old - n, n);      // (1-z)n + z*h
            h_s[u] = hnew;                            // both halves, same value
            if (half == 0) out_b[(c*CH + s)*NHH + u] = hnew;
            h_old = hnew;
            __syncthreads();
        }
        // staged GI prefetch for chunk c+2 into the buffer just consumed
        if (c + 2 < NCHUNK) {
            #pragma unroll
            for (int i = 0; i < 6; i++) {
                int unit = tid + i*128;
                asm volatile("cp.async.ca.shared.global [%0], [%1], 16;"
                    :: "r"(gibase + (c & 1)*(CH*GG*4) + unit*16),
                       "l"(gi_src + (c+2)*CH*GG + unit*4));
            }
            asm volatile("cp.async.commit_group;");
            asm volatile("cp.async.wait_group 1;");   // chunk c+1 complete
        } else {
            asm volatile("cp.async.wait_group 0;");
        }
        __syncthreads();
    }
}

// -------- launch --------
extern "C" void kernel_launch(void* const* d_in, const int* in_sizes, int n_in,
                              void* d_out, int out_size) {
    const float* ts   = (const float*)d_in[0];
    const float* val  = (const float*)d_in[1];
    const int*   mark = (const int*)  d_in[2];
    const float* npm  = (const float*)d_in[3];
    const float* Wl   = (const float*)d_in[4];
    const float* bl   = (const float*)d_in[5];
    const float* Wp   = (const float*)d_in[6];
    const float* bp   = (const float*)d_in[7];
    const float* Wq   = (const float*)d_in[8];
    const float* bq   = (const float*)d_in[9];
    const float* Wk   = (const float*)d_in[10];
    const float* bk   = (const float*)d_in[11];
    const float* Wo   = (const float*)d_in[12];
    const float* bo   = (const float*)d_in[13];
    const float* W_ih = (const float*)d_in[14];
    const float* W_hh = (const float*)d_in[15];
    const float* b_ih = (const float*)d_in[16];
    const float* b_hh = (const float*)d_in[17];
    float* out = (float*)d_out;

    cudaFuncSetAttribute(k_att, cudaFuncAttributeMaxDynamicSharedMemorySize,
                         SM_BYTES);

    k_att<<<128, 256, SM_BYTES>>>(ts, val, mark, npm, Wl, bl, Wp, bp,
                                  Wq, bq, Wk, bk, Wo, bo, W_ih, b_ih);
    k_gru<<<8, 128>>>(W_hh, b_hh, out);
}

// round 15
// speedup vs baseline: 1.3293x; 1.0345x over previous
#include <cuda_runtime.h>
#include <math.h>

#define BB  8
#define LL  512
#define KK  16
#define EE  32
#define NHH 64
#define GG  192
#define CH      16           // GRU: steps per GI prefetch chunk
#define NCHUNK  (LL/CH)      // 32

// -------- scratch: ONLY the GI handoff buffer (no other globals) ----------
__device__ float g_GI[BB*LL*GG];     // input gates (Wo/W_ih folded)

__device__ __forceinline__ float tanh_fast(float x) {
    float y;
    asm("tanh.approx.f32 %0, %1;" : "=f"(y) : "f"(x));
    return y;
}
#define FMA2(acc, x, y) \
    asm("fma.rn.f32x2 %0, %1, %2, %0;" : "+l"(acc) : "l"(x), "l"(y))
#define ADDF2(out, a, b) \
    asm("add.rn.f32x2 %0, %1, %2;" : "=l"(out) : "l"(a), "l"(b))
__device__ __forceinline__ float f2lo(unsigned long long v) {
    return __uint_as_float((unsigned)v);
}
__device__ __forceinline__ float f2hi(unsigned long long v) {
    return __uint_as_float((unsigned)(v >> 32));
}

// smem layout (floats) — att kernel
#define A_S    0                 // 32*512 score tile
#define A_KB   16384             // 64*36 ke tile (rows 0..31 = keq in stages 2-3)
#define A_WQ   (A_KB+2304)       // 32*33
#define A_WK   (A_WQ+1056)       // 32*33
#define A_AM   (A_WK+1056)       // 32*33  A = Wq^T Wk
#define A_QM   (A_AM+1056)       // 32*36  qm rows (16B-aligned stride)
#define A_S0   (A_QM+1152)       // 32
#define A_V1   (A_S0+32)         // 32
#define A_V2   (A_V1+32)         // 32
#define A_BQ   (A_V2+32)         // 32
#define A_BK   (A_BQ+32)         // 32
#define A_C0   (A_BK+32)         // 4 (padded)
#define A_VAL  (A_C0+4)          // 512
#define A_X    (A_VAL+512)       // 512
#define A_M2   (A_X+512)         // 192*17
#define A_CC   (A_M2+3264)       // 192
#define A_INT  (A_CC+192)        // ints: cnt 16, off 16, bidx 512
#define A_MISC (A_INT+544)       // sWp 32, sbp 32, sWl/sbl 2
#define A_WO   (((A_MISC+66+3)/4)*4)   // 1024, 16B-aligned
#define A_BO   (A_WO+1024)       // 64
#define SM_FLOATS (A_BO + 64)
#define SM_BYTES  (SM_FLOATS * 4)

// ============ kernel 1: SELF-CONTAINED attention block (qt, b) =============
// Bilinear trick: S = (Wq keq + bq)·(Wk kek + bk)
//   = (A^T keq + v1)·kek + (v2·keq + c0),  A = Wq^T Wk.
// qm rows precomputed once per block; per-kt k-projection eliminated.
__global__ void __launch_bounds__(256) k_att(
        const float* __restrict__ ts,   const float* __restrict__ val,
        const int*   __restrict__ mark, const float* __restrict__ npm,
        const float* __restrict__ Wl, const float* __restrict__ bl,
        const float* __restrict__ Wp, const float* __restrict__ bp,
        const float* __restrict__ Wq, const float* __restrict__ bq,
        const float* __restrict__ Wk, const float* __restrict__ bk,
        const float* __restrict__ Wo, const float* __restrict__ bo,
        const float* __restrict__ W_ih, const float* __restrict__ b_ih) {
    extern __shared__ float sm[];
    float* S_s   = sm + A_S;
    float* kb    = sm + A_KB;
    float* wq_s  = sm + A_WQ;
    float* wk_s  = sm + A_WK;
    float* A_s   = sm + A_AM;
    float* qm_s  = sm + A_QM;
    float* s0_s  = sm + A_S0;
    float* v1_s  = sm + A_V1;
    float* v2_s  = sm + A_V2;
    float* bq_s  = sm + A_BQ;
    float* bk_s  = sm + A_BK;
    float* val_s = sm + A_VAL;
    float* x_s   = sm + A_X;
    float* M2_s  = sm + A_M2;
    float* cc_s  = sm + A_CC;
    int*   cnt_s  = (int*)(sm + A_INT);
    int*   off_s  = cnt_s + KK;
    int*   bidx_s = off_s + KK;
    float* sWp  = sm + A_MISC;
    float* sbp  = sWp + EE;
    float* sWls = sbp + EE;
    float* wo_s = sm + A_WO;
    float* bo_s = sm + A_BO;

    int blk = blockIdx.x, tid = threadIdx.x;
    int qt = blk >> 3, b = blk & 7;        // 16 qtiles x 8 batches
    int qbase = qt * 32;
    int wid = tid >> 5, lane = tid & 31;
    unsigned smbase = (unsigned)__cvta_generic_to_shared(sm);

    // ---- stage 1: staging + bucket ballots ----
    for (int i = tid; i < EE*EE; i += 256) {
        int e = i >> 5, j = i & 31;
        wq_s[e*33+j] = Wq[i];
        wk_s[e*33+j] = Wk[i];
    }
    if (tid < EE-1) { sWp[tid] = Wp[tid]; sbp[tid] = bp[tid]; }
    if (tid == 0)   { sWls[0] = Wl[0]; sWls[1] = bl[0]; }
    if (tid < EE)   { bq_s[tid] = bq[tid]; bk_s[tid] = bk[tid]; }
    for (int i = tid; i < LL; i += 256) val_s[i] = val[b*LL+i];
    ((float4*)wo_s)[tid] = __ldg(&((const float4*)Wo)[tid]);
    if (tid < NHH) bo_s[tid] = __ldg(&bo[tid]);

    // bucket ballots: 8 warps x 2 categories each (register-local)
    __shared__ int cnt_sh[KK], off_sh[KK];
    unsigned mrec[2][LL/32];
    #pragma unroll
    for (int pass = 0; pass < 2; pass++) {
        int c = wid + pass*8;
        int cnt = 0;
        #pragma unroll
        for (int ch = 0; ch < LL/32; ch++) {
            int k = ch*32 + lane;
            int   mk = mark[b*LL+k];
            float np = npm[b*LL+k];
            bool hit = (mk == c+1) && (np > 0.f);
            unsigned m = __ballot_sync(0xffffffffu, hit);
            mrec[pass][ch] = m;
            cnt += __popc(m);
        }
        if (lane == 0) cnt_sh[c] = cnt;
    }
    __syncthreads();

    // ---- stage 2: A matrix + M2 fold + v1/v2/c0 + scan + keq ----
    // A[a][b] = sum_e Wq[e][a]*Wk[e][b]; thread: a = tid>>3, b0 = (tid&7)*4
    {
        int a = tid >> 3, b0 = (tid & 7) * 4;
        float ac0 = 0.f, ac1 = 0.f, ac2 = 0.f, ac3 = 0.f;
        #pragma unroll
        for (int e = 0; e < EE; e++) {
            float wqv = wq_s[e*33 + a];
            ac0 = fmaf(wqv, wk_s[e*33 + b0+0], ac0);
            ac1 = fmaf(wqv, wk_s[e*33 + b0+1], ac1);
            ac2 = fmaf(wqv, wk_s[e*33 + b0+2], ac2);
            ac3 = fmaf(wqv, wk_s[e*33 + b0+3], ac3);
        }
        A_s[a*33 + b0+0] = ac0;
        A_s[a*33 + b0+1] = ac1;
        A_s[a*33 + b0+2] = ac2;
        A_s[a*33 + b0+3] = ac3;
    }
    // M2 fold (tid < 192)
    if (tid < GG) {
        int g = tid;
        float wrow[NHH];
        const float4* wih4 = (const float4*)(W_ih + (size_t)g*NHH);
        #pragma unroll
        for (int i = 0; i < 16; i++) {
            float4 v = __ldg(&wih4[i]);
            wrow[4*i]   = v.x; wrow[4*i+1] = v.y;
            wrow[4*i+2] = v.z; wrow[4*i+3] = v.w;
        }
        float cc = __ldg(&b_ih[g]);
        unsigned long long acc2[8];
        #pragma unroll
        for (int j = 0; j < 8; j++) acc2[j] = 0ull;
        unsigned woaddr = smbase + A_WO*4;
        #pragma unroll 8
        for (int o = 0; o < NHH; o++) {
            float w = wrow[o];
            cc = fmaf(w, bo_s[o], cc);
            unsigned long long wp;
            asm("mov.b64 %0, {%1, %1};" : "=l"(wp) : "r"(__float_as_uint(w)));
            unsigned ab = woaddr + (unsigned)(o*64);
            #pragma unroll
            for (int j2 = 0; j2 < 4; j2++) {
                unsigned long long x, y;
                asm volatile("ld.shared.v2.u64 {%0, %1}, [%2];"
                             : "=l"(x), "=l"(y) : "r"(ab + j2*16));
                FMA2(acc2[2*j2],   wp, x);
                FMA2(acc2[2*j2+1], wp, y);
            }
        }
        cc_s[g] = cc;
        #pragma unroll
        for (int j = 0; j < 8; j++) {
            M2_s[g*17 + 2*j]   = f2lo(acc2[j]);
            M2_s[g*17 + 2*j+1] = f2hi(acc2[j]);
        }
    } else if (wid == 6) {
        // v1[b] = Wk^T bq; v2[a] = Wq^T bk (warp 6, lane = index)
        float a1 = 0.f, a2 = 0.f;
        #pragma unroll
        for (int e = 0; e < EE; e++) {
            a1 = fmaf(wk_s[e*33 + lane], bq_s[e], a1);
            a2 = fmaf(wq_s[e*33 + lane], bk_s[e], a2);
        }
        v1_s[lane] = a1;
        v2_s[lane] = a2;
    } else if (tid == 224) {
        float c0 = 0.f;
        #pragma unroll
        for (int e = 0; e < EE; e++) c0 = fmaf(bq_s[e], bk_s[e], c0);
        sm[A_C0] = c0;
    }
    if (tid == 0) {
        int acc = 0;
        #pragma unroll
        for (int i = 0; i < KK; i++) { off_sh[i] = acc; acc += cnt_sh[i]; }
    }
    // keq: 32 q-rows into kb (stride 36)
    for (int idx = tid; idx < 32*EE; idx += 256) {
        int r = idx >> 5, i = idx & 31;
        float t = ts[b*LL + qbase + r];
        kb[r*36 + i] = (i == 0) ? fmaf(t, sWls[0], sWls[1])
                                : __sinf(fmaf(t, sWp[i-1], sbp[i-1]));
    }
    __syncthreads();

    // ---- stage 3: bucket compaction + qm rows + s0 ----
    #pragma unroll
    for (int pass = 0; pass < 2; pass++) {
        int c = wid + pass*8;
        int off = off_sh[c], pos = 0;
        #pragma unroll
        for (int ch = 0; ch < LL/32; ch++) {
            unsigned m = mrec[pass][ch];
            if ((m >> lane) & 1u)
                bidx_s[off + pos + __popc(m & ((1u<<lane)-1u))] = ch*32 + lane;
            pos += __popc(m);
        }
        if (lane == 0) { cnt_s[c] = cnt_sh[c]; off_s[c] = off; }
    }
    // qm[q][b] = sum_a keq[q][a]*A[a][b] + v1[b]; thread: q = tid>>3, b0 = (tid&7)*4
    {
        int q = tid >> 3, b0 = (tid & 7) * 4;
        float ac0 = v1_s[b0+0], ac1 = v1_s[b0+1], ac2 = v1_s[b0+2], ac3 = v1_s[b0+3];
        #pragma unroll
        for (int a = 0; a < EE; a++) {
            float kv = kb[q*36 + a];
            ac0 = fmaf(kv, A_s[a*33 + b0+0], ac0);
            ac1 = fmaf(kv, A_s[a*33 + b0+1], ac1);
            ac2 = fmaf(kv, A_s[a*33 + b0+2], ac2);
            ac3 = fmaf(kv, A_s[a*33 + b0+3], ac3);
        }
        qm_s[q*36 + b0+0] = ac0;
        qm_s[q*36 + b0+1] = ac1;
        qm_s[q*36 + b0+2] = ac2;
        qm_s[q*36 + b0+3] = ac3;
    }
    if (tid < 32) {
        float a = sm[A_C0];
        #pragma unroll
        for (int j = 0; j < EE; j++) a = fmaf(v2_s[j], kb[tid*36 + j], a);
        s0_s[tid] = a;
    }
    __syncthreads();

    // ---- stage 4: q2 registers from qm row + s0 scalar ----
    int ql4 = tid >> 3, kg = tid & 7;        // 32 q-rows x 8 k-groups
    unsigned kaddr = smbase + A_KB*4;
    unsigned long long q2[16];
    {
        unsigned qrow = smbase + A_QM*4 + (unsigned)(ql4*36*4);
        #pragma unroll
        for (int i = 0; i < 8; i++) {
            asm volatile("ld.shared.v2.u64 {%0, %1}, [%2];"
                         : "=l"(q2[2*i]), "=l"(q2[2*i+1]) : "r"(qrow + i*16));
        }
    }
    float s0v = s0_s[ql4];
    __syncthreads();

    // ---- stage 5: per k-tile (ke-gen -> GEMM), NO k-projection ----
    const float sc = 0.17677669529663687f;   // 1/sqrt(32)
    for (int kt = 0; kt < 8; kt++) {
        for (int idx = tid; idx < 64*EE; idx += 256) {
            int r = idx >> 5, i = idx & 31;
            float t = ts[b*LL + kt*64 + r];
            kb[r*36 + i] = (i == 0) ? fmaf(t, sWls[0], sWls[1])
                                    : __sinf(fmaf(t, sWp[i-1], sbp[i-1]));
        }
        __syncthreads();
        // GEMM: S[q][k] = qm_q . ke_k + s0_q ; rows kg+8m, conflict-free
        unsigned long long acc[8];
        #pragma unroll
        for (int m = 0; m < 8; m++) acc[m] = 0ull;
        #pragma unroll
        for (int m = 0; m < 8; m++) {
            unsigned rb = kaddr + (unsigned)((kg + 8*m)*36*4);
            #pragma unroll
            for (int j = 0; j < 8; j++) {
                unsigned long long hx, hy;
                asm volatile("ld.shared.v2.u64 {%0, %1}, [%2];"
                             : "=l"(hx), "=l"(hy) : "r"(rb + j*16));
                FMA2(acc[m], q2[2*j], hx); FMA2(acc[m], q2[2*j+1], hy);
            }
        }
        float* so = &S_s[ql4*LL + kt*64 + kg];
        #pragma unroll
        for (int m = 0; m < 8; m++)
            so[8*m] = (f2lo(acc[m]) + f2hi(acc[m]) + s0v)*sc;
        __syncthreads();
    }

    // ---- stage 6: bucketed softmax, THREAD per (ql,c), plain-sum exp ----
    for (int task = tid; task < 32*KK; task += 256) {
        int ql = task >> 4, c = task & 15;
        int q = qbase + ql;
        int off = off_s[c], cnt = cnt_s[c];
        float se = 0.f, sv = 0.f;
        for (int i = 0; i < cnt; i++) {
            int   kk = bidx_s[off + i];
            float lg = (kk <= q+1) ? fminf(S_s[ql*LL + kk], 80.f) : 0.f;
            float ex = __expf(lg);
            se += ex;
            sv += ex * val_s[kk];
        }
        x_s[ql*KK + c] = (cnt > 0) ? sv/se : 0.f;
    }
    __syncthreads();

    // ---- stage 7: GI[b,q,g] = cc[g] + sum_c M2[g][c] * x[q][c] ----
    for (int o = tid; o < 32*GG; o += 256) {
        int ql = o / GG, g = o - ql*GG;
        float acc = cc_s[g];
        #pragma unroll
        for (int c = 0; c < KK; c++) acc += M2_s[g*17+c] * x_s[ql*KK+c];
        g_GI[((size_t)(b*LL) + qbase + ql)*GG + g] = acc;
    }
}

// ============ kernel 2: GRU scan (round-14 passing version) ================
__global__ void __launch_bounds__(128) k_gru(const float* __restrict__ W_hh,
                                             const float* __restrict__ b_hh,
                                             float* __restrict__ out) {
    int b = blockIdx.x, tid = threadIdx.x;
    int u = tid >> 1, half = tid & 1;
    __shared__ __align__(16) float h_s[NHH];
    __shared__ __align__(16) float gi_s[2][CH*GG];

    // weights: rows u / 64+u / 128+u, k-slice [half*32,+32), packed f32x2
    unsigned long long wr[16], wz[16], wn[16];
    {
        const ulonglong2* r2 = (const ulonglong2*)(W_hh + (size_t)u*NHH       + half*32);
        const ulonglong2* z2 = (const ulonglong2*)(W_hh + (size_t)(64+u)*NHH  + half*32);
        const ulonglong2* n2 = (const ulonglong2*)(W_hh + (size_t)(128+u)*NHH + half*32);
        #pragma unroll
        for (int i = 0; i < 8; i++) {
            ulonglong2 a = r2[i]; wr[2*i] = a.x; wr[2*i+1] = a.y;
            ulonglong2 c = z2[i]; wz[2*i] = c.x; wz[2*i+1] = c.y;
            ulonglong2 d = n2[i]; wn[2*i] = d.x; wn[2*i+1] = d.y;
        }
    }
    float br = b_hh[u], bz = b_hh[64+u], bn = b_hh[128+u];
    float h_old = 0.f;
    if (tid < NHH) h_s[tid] = 0.f;

    unsigned haddr = (unsigned)__cvta_generic_to_shared(h_s) + half*128;
    unsigned gibase = (unsigned)__cvta_generic_to_shared(gi_s);
    const float* gi_src = g_GI + (size_t)b*LL*GG;
    float* out_b = out + (size_t)b*LL*NHH;

    // prologue: prefetch chunks 0 and 1
    #pragma unroll
    for (int cpre = 0; cpre < 2; cpre++) {
        #pragma unroll
        for (int i = 0; i < 6; i++) {
            int unit = tid + i*128;               // 768 x 16B per chunk
            asm volatile("cp.async.ca.shared.global [%0], [%1], 16;"
                :: "r"(gibase + cpre*(CH*GG*4) + unit*16),
                   "l"(gi_src + cpre*CH*GG + unit*4));
        }
        asm volatile("cp.async.commit_group;");
    }
    asm volatile("cp.async.wait_group 1;");
    __syncthreads();

    for (int c = 0; c < NCHUNK; c++) {
        const float* gi = (const float*)gi_s[c & 1];
        #pragma unroll 4
        for (int s = 0; s < CH; s++) {
            // gate inputs first (LDS latency overlaps with matvec)
            float gr = gi[s*GG + u], gz = gi[s*GG + 64 + u], gn = gi[s*GG + 128 + u];
            // half-matvec: 8x LDS.128 of h-half, 48 FMA2 over 6 chains
            unsigned long long ar0=0ull, ar1=0ull, az0=0ull, az1=0ull,
                               an0=0ull, an1=0ull;
            #pragma unroll
            for (int i = 0; i < 8; i++) {
                unsigned long long hx, hy;
                asm volatile("ld.shared.v2.u64 {%0, %1}, [%2];"
                             : "=l"(hx), "=l"(hy) : "r"(haddr + i*16));
                FMA2(ar0, wr[2*i], hx); FMA2(ar1, wr[2*i+1], hy);
                FMA2(az0, wz[2*i], hx); FMA2(az1, wz[2*i+1], hy);
                FMA2(an0, wn[2*i], hx); FMA2(an1, wn[2*i+1], hy);
            }
            unsigned long long arT, azT, anT;
            ADDF2(arT, ar0, ar1);
            ADDF2(azT, az0, az1);
            ADDF2(anT, an0, an1);
            float sr = f2lo(arT) + f2hi(arT);
            float sz = f2lo(azT) + f2hi(azT);
            float sn = f2lo(anT) + f2hi(anT);
            sr += __shfl_xor_sync(0xffffffffu, sr, 1);
            sz += __shfl_xor_sync(0xffffffffu, sz, 1);
            sn += __shfl_xor_sync(0xffffffffu, sn, 1);

            float snb  = sn + bn;
            float hsn  = 0.5f * snb;
            float base = gn + hsn;
            float t_r  = tanh_fast(0.5f * (gr + sr + br));
            float t_z  = tanh_fast(0.5f * (gz + sz + bz));
            float n    = tanh_fast(fmaf(hsn, t_r, base));
            float z    = fmaf(0.5f, t_z, 0.5f);
            float hnew = fmaf(z, h_old - n, n);      // (1-z)n + z*h
            h_s[u] = hnew;                            // both halves, same value
            if (half == 0) out_b[(c*CH + s)*NHH + u] = hnew;
            h_old = hnew;
            __syncthreads();
        }
        // staged GI prefetch for chunk c+2 into the buffer just consumed
        if (c + 2 < NCHUNK) {
            #pragma unroll
            for (int i = 0; i < 6; i++) {
                int unit = tid + i*128;
                asm volatile("cp.async.ca.shared.global [%0], [%1], 16;"
                    :: "r"(gibase + (c & 1)*(CH*GG*4) + unit*16),
                       "l"(gi_src + (c+2)*CH*GG + unit*4));
            }
            asm volatile("cp.async.commit_group;");
            asm volatile("cp.async.wait_group 1;");   // chunk c+1 complete
        } else {
            asm volatile("cp.async.wait_group 0;");
        }
        __syncthreads();
    }
}

// -------- launch --------
extern "C" void kernel_launch(void* const* d_in, const int* in_sizes, int n_in,
                              void* d_out, int out_size) {
    const float* ts   = (const float*)d_in[0];
    const float* val  = (const float*)d_in[1];
    const int*   mark = (const int*)  d_in[2];
    const float* npm  = (const float*)d_in[3];
    const float* Wl   = (const float*)d_in[4];
    const float* bl   = (const float*)d_in[5];
    const float* Wp   = (const float*)d_in[6];
    const float* bp   = (const float*)d_in[7];
    const float* Wq   = (const float*)d_in[8];
    const float* bq   = (const float*)d_in[9];
    const float* Wk   = (const float*)d_in[10];
    const float* bk   = (const float*)d_in[11];
    const float* Wo   = (const float*)d_in[12];
    const float* bo   = (const float*)d_in[13];
    const float* W_ih = (const float*)d_in[14];
    const float* W_hh = (const float*)d_in[15];
    const float* b_ih = (const float*)d_in[16];
    const float* b_hh = (const float*)d_in[17];
    float* out = (float*)d_out;

    cudaFuncSetAttribute(k_att, cudaFuncAttributeMaxDynamicSharedMemorySize,
                         SM_BYTES);

    k_att<<<128, 256, SM_BYTES>>>(ts, val, mark, npm, Wl, bl, Wp, bp,
                                  Wq, bq, Wk, bk, Wo, bo, W_ih, b_ih);
    k_gru<<<8, 128>>>(W_hh, b_hh, out);
}